// round 8
// baseline (speedup 1.0000x reference)
#include <cuda_runtime.h>

#define BH     32
#define LSEQ   4096
#define D      128
#define C      32
#define NCHUNK 128
#define NSPLIT 4

// Scratch (device globals are the allowed scratch mechanism)
__device__ __align__(16) float g_qn[(size_t)BH * LSEQ * D];
__device__ __align__(16) float g_kn[(size_t)BH * LSEQ * D];
__device__ __align__(16) float g_u [(size_t)BH * LSEQ * D];
__device__ __align__(16) float g_w [(size_t)BH * LSEQ * D];
__device__ __align__(16) float g_attn[(size_t)BH * NCHUNK * C * C];

// ---------------------------------------------------------------------------
// Kernel 1: l2-normalize q and k rows. One warp per row (handles q & k rows).
// ---------------------------------------------------------------------------
__global__ void norm_kernel(const float* __restrict__ q,
                            const float* __restrict__ k) {
    int warp = threadIdx.x >> 5;
    int lane = threadIdx.x & 31;
    size_t row = (size_t)blockIdx.x * 8 + warp;   // 0 .. BH*LSEQ-1

    {
        float4 a = ((const float4*)q)[row * 32 + lane];
        float ss = a.x * a.x + a.y * a.y + a.z * a.z + a.w * a.w;
        #pragma unroll
        for (int o = 16; o; o >>= 1) ss += __shfl_xor_sync(0xffffffffu, ss, o);
        float r = rsqrtf(ss + 1e-6f);
        float4 o4 = make_float4(a.x * r, a.y * r, a.z * r, a.w * r);
        ((float4*)g_qn)[row * 32 + lane] = o4;
    }
    {
        float4 a = ((const float4*)k)[row * 32 + lane];
        float ss = a.x * a.x + a.y * a.y + a.z * a.z + a.w * a.w;
        #pragma unroll
        for (int o = 16; o; o >>= 1) ss += __shfl_xor_sync(0xffffffffu, ss, o);
        float r = rsqrtf(ss + 1e-6f);
        float4 o4 = make_float4(a.x * r, a.y * r, a.z * r, a.w * r);
        ((float4*)g_kn)[row * 32 + lane] = o4;
    }
}

// ---------------------------------------------------------------------------
// Kernel 2: per chunk (4096 blocks, 128 threads):
//   A = -(k_beta @ kn^T) * strict_lower; forward substitution; then
//   u = (A+I) @ (beta*v), w = (A+I) @ (beta*kn), attn = (qn @ kn^T)*tril
// ---------------------------------------------------------------------------
__global__ void chunk_kernel(const float* __restrict__ v,
                             const float* __restrict__ beta) {
    __shared__ float knT[128 * 33];     // transposed kn tile, pad 33
    __shared__ float qn_s[32 * 128];
    __shared__ float A[32 * 33];
    __shared__ float beta_s[32];

    int tid = threadIdx.x;              // 128 threads
    size_t cid = blockIdx.x;            // bh*128 + chunk
    size_t base = cid * 32;             // row base = bh*LSEQ + chunk*32

    for (int idx = tid; idx < 4096; idx += 128) {
        int r = idx >> 7, d = idx & 127;
        knT[d * 33 + r] = g_kn[(base + r) * 128 + d];
        qn_s[idx] = g_qn[base * 128 + idx];
    }
    if (tid < 32) beta_s[tid] = beta[base + tid];
    __syncthreads();

    int j = tid & 31, iw = tid >> 5;    // iw in 0..3, rows i = iw*8+ii

    // A = -(beta_i * kn_i . kn_j), strictly lower
    {
        float acc[8] = {0, 0, 0, 0, 0, 0, 0, 0};
        for (int d = 0; d < 128; d++) {
            float kj = knT[d * 33 + j];
            #pragma unroll
            for (int ii = 0; ii < 8; ii++)
                acc[ii] += knT[d * 33 + (iw * 8 + ii)] * kj;
        }
        #pragma unroll
        for (int ii = 0; ii < 8; ii++) {
            int i = iw * 8 + ii;
            A[i * 33 + j] = (i > j) ? (-beta_s[i] * acc[ii]) : 0.0f;
        }
    }
    __syncthreads();

    // Forward substitution (warp 0): A[i, :i] += A[i, :] @ A[:, :i]
    if (tid < 32) {
        for (int i = 1; i < 32; i++) {
            float upd = 0.0f;
            for (int t = tid + 1; t < i; t++)
                upd += A[i * 33 + t] * A[t * 33 + tid];
            __syncwarp();
            if (tid < i) A[i * 33 + tid] += upd;
            __syncwarp();
        }
    }
    __syncthreads();

    // attn = (qn @ kn^T) with lower-inclusive mask
    {
        float acc[8] = {0, 0, 0, 0, 0, 0, 0, 0};
        for (int d = 0; d < 128; d++) {
            float kj = knT[d * 33 + j];
            #pragma unroll
            for (int ii = 0; ii < 8; ii++)
                acc[ii] += qn_s[(iw * 8 + ii) * 128 + d] * kj;
        }
        float* ga = g_attn + cid * 1024;
        #pragma unroll
        for (int ii = 0; ii < 8; ii++) {
            int i = iw * 8 + ii;
            ga[i * 32 + j] = (i >= j) ? acc[ii] : 0.0f;
        }
    }

    // u = (A+I) @ (beta*v),  w = (A+I) @ (beta*kn)
    {
        int d32 = tid & 31;              // 4 cols: d32*4 .. d32*4+3
        int cw  = tid >> 5;              // 8 rows: cw*8 .. cw*8+7
        float4 au[8], aw[8];
        #pragma unroll
        for (int ii = 0; ii < 8; ii++) {
            int c = cw * 8 + ii;
            float4 vv = *(const float4*)&v[(base + c) * 128 + d32 * 4];
            float4 kk = *(const float4*)&g_kn[(base + c) * 128 + d32 * 4];
            float bc = beta_s[c];
            au[ii] = make_float4(vv.x * bc, vv.y * bc, vv.z * bc, vv.w * bc);
            aw[ii] = make_float4(kk.x * bc, kk.y * bc, kk.z * bc, kk.w * bc);
        }
        for (int t = 0; t < 32; t++) {
            float bt = beta_s[t];
            float4 vv = *(const float4*)&v[(base + t) * 128 + d32 * 4];
            float4 kk = *(const float4*)&g_kn[(base + t) * 128 + d32 * 4];
            vv.x *= bt; vv.y *= bt; vv.z *= bt; vv.w *= bt;
            kk.x *= bt; kk.y *= bt; kk.z *= bt; kk.w *= bt;
            #pragma unroll
            for (int ii = 0; ii < 8; ii++) {
                float a = A[(cw * 8 + ii) * 33 + t];
                au[ii].x += a * vv.x; au[ii].y += a * vv.y;
                au[ii].z += a * vv.z; au[ii].w += a * vv.w;
                aw[ii].x += a * kk.x; aw[ii].y += a * kk.y;
                aw[ii].z += a * kk.z; aw[ii].w += a * kk.w;
            }
        }
        #pragma unroll
        for (int ii = 0; ii < 8; ii++) {
            int c = cw * 8 + ii;
            *(float4*)&g_u[(base + c) * 128 + d32 * 4] = au[ii];
            *(float4*)&g_w[(base + c) * 128 + d32 * 4] = aw[ii];
        }
    }
}

// ---------------------------------------------------------------------------
// cp.async helpers
// ---------------------------------------------------------------------------
__device__ __forceinline__ void cpa16(float* s, const void* g) {
    unsigned a = (unsigned)__cvta_generic_to_shared(s);
    asm volatile("cp.async.cg.shared.global [%0], [%1], 16;" :: "r"(a), "l"(g));
}
__device__ __forceinline__ void cpa_commit() {
    asm volatile("cp.async.commit_group;");
}
__device__ __forceinline__ void cpa_wait_all() {
    asm volatile("cp.async.wait_group 0;");
}

// Buffer layout (floats, per buffer):
//   q[4096] @0, k[4096] @4096, w[4096] @8192, attn[1024] @12288, u0[1024] @13312
#define OFF_Q    0
#define OFF_K    4096
#define OFF_W    8192
#define OFF_A    12288
#define OFF_U0   13312
#define BUF_FLOATS 14336

// ---------------------------------------------------------------------------
// Kernel 3: sequential scan over chunks. grid (NSPLIT, BH), 512 threads
// (16 warps = 4 per SMSP for latency hiding). Double-buffered cp.async
// prefetch; fused (w@S, q@S) d-loop; two barriers per chunk.
// ---------------------------------------------------------------------------
__global__ void __launch_bounds__(512, 1) scan_kernel(float* __restrict__ out) {
    extern __shared__ float sm[];
    float* S  = sm;                             // 128*32 = 4096
    float* us = sm + 4096 + 2 * BUF_FLOATS;     // 32*32

    int tid = threadIdx.x;
    int bh = blockIdx.y;
    int dvoff = blockIdx.x * 32;
    int j = tid & 31;              // dv column within slice
    int cg = tid >> 5;             // warp id 0..15: rows c = cg*2, cg*2+1

    const float4* gq4 = (const float4*)(g_qn + (size_t)bh * LSEQ * D);
    const float4* gk4 = (const float4*)(g_kn + (size_t)bh * LSEQ * D);
    const float4* gw4 = (const float4*)(g_w  + (size_t)bh * LSEQ * D);
    const float4* ga4 = (const float4*)(g_attn + (size_t)bh * NCHUNK * 1024);
    const float*  gu  = g_u + (size_t)bh * LSEQ * D;
    float* gout = out + (size_t)bh * LSEQ * D + dvoff;

    // ---- prefetch chunk 0 into buffer 0
    {
        float* B = sm + 4096;
        #pragma unroll
        for (int it = 0; it < 2; it++) {
            int i = tid + it * 512;
            cpa16(B + OFF_Q + 4 * i, gq4 + i);
            cpa16(B + OFF_K + 4 * i, gk4 + i);
            cpa16(B + OFF_W + 4 * i, gw4 + i);
        }
        if (tid < 256) {
            cpa16(B + OFF_A + 4 * tid, ga4 + tid);
            int row = tid >> 3, c4 = tid & 7;
            cpa16(B + OFF_U0 + 4 * tid,
                  gu + (size_t)row * 128 + dvoff + c4 * 4);
        }
        cpa_commit();
    }

    for (int i = tid; i < 4096; i += 512) S[i] = 0.0f;

    for (int ch = 0; ch < NCHUNK; ch++) {
        cpa_wait_all();
        __syncthreads();   // current buffer ready; prev chunk's S update done

        float* B = sm + 4096 + (ch & 1) * BUF_FLOATS;
        const float4* qs4 = (const float4*)(B + OFF_Q);
        const float4* ks4 = (const float4*)(B + OFF_K);
        const float4* ws4 = (const float4*)(B + OFF_W);
        const float4* as4 = (const float4*)(B + OFF_A);
        const float*  u0b = B + OFF_U0;

        // ---- prefetch chunk ch+1 into the other buffer (overlaps compute)
        if (ch + 1 < NCHUNK) {
            float* P = sm + 4096 + ((ch + 1) & 1) * BUF_FLOATS;
            size_t off4 = (size_t)(ch + 1) * 1024;
            #pragma unroll
            for (int it = 0; it < 2; it++) {
                int i = tid + it * 512;
                cpa16(P + OFF_Q + 4 * i, gq4 + off4 + i);
                cpa16(P + OFF_K + 4 * i, gk4 + off4 + i);
                cpa16(P + OFF_W + 4 * i, gw4 + off4 + i);
            }
            if (tid < 256) {
                cpa16(P + OFF_A + 4 * tid, ga4 + (size_t)(ch + 1) * 256 + tid);
                int row = tid >> 3, c4 = tid & 7;
                cpa16(P + OFF_U0 + 4 * tid,
                      gu + (size_t)((ch + 1) * 32 + row) * 128 + dvoff + c4 * 4);
            }
            cpa_commit();
        }

        // ---- fused step: u_i = u0 - w_i @ S  and  oq = q_i @ S  (2 rows/warp)
        float accU[2], accO[2];
        #pragma unroll
        for (int cc = 0; cc < 2; cc++) {
            accU[cc] = u0b[(cg * 2 + cc) * 32 + j];
            accO[cc] = 0.0f;
        }
        for (int d4 = 0; d4 < 32; d4++) {
            float s0 = S[(d4 * 4 + 0) * 32 + j];
            float s1 = S[(d4 * 4 + 1) * 32 + j];
            float s2 = S[(d4 * 4 + 2) * 32 + j];
            float s3 = S[(d4 * 4 + 3) * 32 + j];
            #pragma unroll
            for (int cc = 0; cc < 2; cc++) {
                float4 w4 = ws4[(cg * 2 + cc) * 32 + d4];
                float4 q4 = qs4[(cg * 2 + cc) * 32 + d4];
                accU[cc] -= w4.x * s0 + w4.y * s1 + w4.z * s2 + w4.w * s3;
                accO[cc] += q4.x * s0 + q4.y * s1 + q4.z * s2 + q4.w * s3;
            }
        }
        #pragma unroll
        for (int cc = 0; cc < 2; cc++)
            us[(cg * 2 + cc) * 32 + j] = accU[cc];
        __syncthreads();   // us ready; all S reads complete

        // ---- out += attn @ u_i ; store (2 rows/warp)
        for (int t4 = 0; t4 < 8; t4++) {
            float u0 = us[(t4 * 4 + 0) * 32 + j];
            float u1 = us[(t4 * 4 + 1) * 32 + j];
            float u2 = us[(t4 * 4 + 2) * 32 + j];
            float u3 = us[(t4 * 4 + 3) * 32 + j];
            #pragma unroll
            for (int cc = 0; cc < 2; cc++) {
                float4 a4 = as4[(cg * 2 + cc) * 8 + t4];
                accO[cc] += a4.x * u0 + a4.y * u1 + a4.z * u2 + a4.w * u3;
            }
        }
        #pragma unroll
        for (int cc = 0; cc < 2; cc++)
            gout[(size_t)(ch * 32 + cg * 2 + cc) * 128 + j] = accO[cc];

        // ---- S += k_i^T @ u_i  (8 disjoint S rows per warp; no barrier:
        //      all S reads finished before the us barrier above)
        int dbase = cg * 8;
        float sacc[8];
        #pragma unroll
        for (int dd = 0; dd < 8; dd++)
            sacc[dd] = S[(dbase + dd) * 32 + j];
        for (int c = 0; c < 32; c++) {
            float uv = us[c * 32 + j];
            #pragma unroll
            for (int dq = 0; dq < 2; dq++) {
                float4 k4 = ks4[c * 32 + cg * 2 + dq];
                sacc[dq * 4 + 0] += k4.x * uv;
                sacc[dq * 4 + 1] += k4.y * uv;
                sacc[dq * 4 + 2] += k4.z * uv;
                sacc[dq * 4 + 3] += k4.w * uv;
            }
        }
        #pragma unroll
        for (int dd = 0; dd < 8; dd++)
            S[(dbase + dd) * 32 + j] = sacc[dd];
        // next iteration's top barrier orders these writes before S reads
    }
}

// ---------------------------------------------------------------------------
extern "C" void kernel_launch(void* const* d_in, const int* in_sizes, int n_in,
                              void* d_out, int out_size) {
    const float* q    = (const float*)d_in[0];
    const float* k    = (const float*)d_in[1];
    const float* v    = (const float*)d_in[2];
    const float* beta = (const float*)d_in[3];
    float* out = (float*)d_out;

    norm_kernel<<<BH * LSEQ / 8, 256>>>(q, k);
    chunk_kernel<<<BH * NCHUNK, 128>>>(v, beta);

    const int smem_bytes = (4096 + 2 * BUF_FLOATS + 1024) * sizeof(float); // 132 KB
    cudaFuncSetAttribute(scan_kernel,
                         cudaFuncAttributeMaxDynamicSharedMemorySize, smem_bytes);
    scan_kernel<<<dim3(NSPLIT, BH), 512, smem_bytes>>>(out);
}

// round 9
// speedup vs baseline: 1.1439x; 1.1439x over previous
#include <cuda_runtime.h>

#define BH     32
#define LSEQ   4096
#define D      128
#define C      32
#define NCHUNK 128
#define NSPLIT 4

typedef unsigned long long ull;

// Scratch (device globals are the allowed scratch mechanism)
__device__ __align__(16) float g_qt[(size_t)BH * LSEQ * D];   // [bh][chunk][d*32+c] (transposed)
__device__ __align__(16) float g_kn[(size_t)BH * LSEQ * D];   // row-major normalized k
__device__ __align__(16) float g_u [(size_t)BH * LSEQ * D];   // row-major
__device__ __align__(16) float g_wt[(size_t)BH * LSEQ * D];   // [bh][chunk][d*32+c] (transposed)
__device__ __align__(16) float g_attn[(size_t)BH * NCHUNK * C * C];  // attn^T: [t][c]

// ---------------------------------------------------------------------------
// f32x2 packed helpers
// ---------------------------------------------------------------------------
__device__ __forceinline__ void fma2(ull& acc, ull a, ull b) {
    asm("fma.rn.f32x2 %0, %1, %2, %0;" : "+l"(acc) : "l"(a), "l"(b));
}
__device__ __forceinline__ ull packdup(float s) {
    ull r;
    asm("mov.b64 %0, {%1, %1};" : "=l"(r) : "r"(__float_as_uint(s)));
    return r;
}
__device__ __forceinline__ ull pack2(float lo, float hi) {
    ull r;
    asm("mov.b64 %0, {%1, %2};" : "=l"(r) : "r"(__float_as_uint(lo)), "r"(__float_as_uint(hi)));
    return r;
}
__device__ __forceinline__ void unpack2(ull v, float& lo, float& hi) {
    unsigned a, b;
    asm("mov.b64 {%0, %1}, %2;" : "=r"(a), "=r"(b) : "l"(v));
    lo = __uint_as_float(a); hi = __uint_as_float(b);
}

// ---------------------------------------------------------------------------
// Kernel 1 (fused norm + chunk): per chunk (4096 blocks, 128 threads).
//   Normalizes q,k rows on load. Computes A = -(kb@kn^T)*strict_lower,
//   forward substitution, attn^T, u = T@(beta v) (row-major),
//   w = T@(beta kn) written TRANSPOSED to g_wt, qn written TRANSPOSED to g_qt.
// ---------------------------------------------------------------------------
__global__ void chunk_kernel(const float* __restrict__ q,
                             const float* __restrict__ k,
                             const float* __restrict__ v,
                             const float* __restrict__ beta) {
    __shared__ float knT[128 * 33];     // k^T (normalized), stride-33; later reused as wT staging
    __shared__ float qnT[128 * 33];     // q^T (normalized), stride-33
    __shared__ float A[32 * 33];
    __shared__ float beta_s[32];

    int tid = threadIdx.x;              // 128 threads
    int lane = tid & 31, wrp = tid >> 5;
    size_t cid = blockIdx.x;            // bh*128 + chunk
    size_t base = cid * 32;             // row base = bh*LSEQ + chunk*32

    // ---- Phase 1: load + l2-normalize (warp per row, 8 rows/warp)
    const float4* q4 = (const float4*)q;
    const float4* k4 = (const float4*)k;
    float4* gkn4 = (float4*)g_kn;
    #pragma unroll
    for (int rr = 0; rr < 8; rr++) {
        int r = wrp * 8 + rr;
        {
            float4 kk = k4[(base + r) * 32 + lane];
            float ss = kk.x * kk.x + kk.y * kk.y + kk.z * kk.z + kk.w * kk.w;
            #pragma unroll
            for (int o = 16; o; o >>= 1) ss += __shfl_xor_sync(0xffffffffu, ss, o);
            float rn = rsqrtf(ss + 1e-6f);
            kk.x *= rn; kk.y *= rn; kk.z *= rn; kk.w *= rn;
            gkn4[(base + r) * 32 + lane] = kk;
            knT[(lane * 4 + 0) * 33 + r] = kk.x;
            knT[(lane * 4 + 1) * 33 + r] = kk.y;
            knT[(lane * 4 + 2) * 33 + r] = kk.z;
            knT[(lane * 4 + 3) * 33 + r] = kk.w;
        }
        {
            float4 qq = q4[(base + r) * 32 + lane];
            float ss = qq.x * qq.x + qq.y * qq.y + qq.z * qq.z + qq.w * qq.w;
            #pragma unroll
            for (int o = 16; o; o >>= 1) ss += __shfl_xor_sync(0xffffffffu, ss, o);
            float rn = rsqrtf(ss + 1e-6f);
            qq.x *= rn; qq.y *= rn; qq.z *= rn; qq.w *= rn;
            qnT[(lane * 4 + 0) * 33 + r] = qq.x;
            qnT[(lane * 4 + 1) * 33 + r] = qq.y;
            qnT[(lane * 4 + 2) * 33 + r] = qq.z;
            qnT[(lane * 4 + 3) * 33 + r] = qq.w;
        }
    }
    if (tid < 32) beta_s[tid] = beta[base + tid];
    __syncthreads();

    int j = lane, iw = wrp;             // rows i = iw*8+ii

    // ---- Phase 2: A = -(beta_i * kn_i . kn_j), strictly lower
    {
        float acc[8] = {0, 0, 0, 0, 0, 0, 0, 0};
        for (int d = 0; d < 128; d++) {
            float kj = knT[d * 33 + j];
            #pragma unroll
            for (int ii = 0; ii < 8; ii++)
                acc[ii] += knT[d * 33 + (iw * 8 + ii)] * kj;
        }
        #pragma unroll
        for (int ii = 0; ii < 8; ii++) {
            int i = iw * 8 + ii;
            A[i * 33 + j] = (i > j) ? (-beta_s[i] * acc[ii]) : 0.0f;
        }
    }
    __syncthreads();

    // ---- Phase 3: forward substitution (warp 0)
    if (tid < 32) {
        for (int i = 1; i < 32; i++) {
            float upd = 0.0f;
            for (int t = tid + 1; t < i; t++)
                upd += A[i * 33 + t] * A[t * 33 + tid];
            __syncwarp();
            if (tid < i) A[i * 33 + tid] += upd;
            __syncwarp();
        }
    }
    __syncthreads();

    // ---- Phase 4: attn^T[jrow][ilane] = qn_i . kn_j, keep when i >= j.
    //      Also drain qnT -> g_qt (transposed layout [d*32+c]).
    {
        float acc[8] = {0, 0, 0, 0, 0, 0, 0, 0};
        for (int d = 0; d < 128; d++) {
            float qv = qnT[d * 33 + lane];          // lane-varying, conflict-free
            #pragma unroll
            for (int ii = 0; ii < 8; ii++)
                acc[ii] += knT[d * 33 + (iw * 8 + ii)] * qv;  // broadcast
        }
        float* ga = g_attn + cid * 1024;
        #pragma unroll
        for (int ii = 0; ii < 8; ii++) {
            int jr = iw * 8 + ii;
            ga[jr * 32 + lane] = (lane >= jr) ? acc[ii] : 0.0f;
        }
        float* gq = g_qt + base * 128;
        for (int idx = tid; idx < 4096; idx += 128) {
            int d = idx >> 5, c = idx & 31;
            gq[idx] = qnT[d * 33 + c];              // read stride-1 across tid
        }
    }
    __syncthreads();   // attn^T done reading knT; safe to reuse knT as wT staging

    // ---- Phase 5: u = (A+I)@(beta*v) -> g_u (row-major);
    //               w = (A+I)@(beta*kn) -> staged transposed in knT -> g_wt
    {
        int d32 = lane;                  // 4 cols: d32*4 .. d32*4+3
        int cw  = wrp;                   // 8 rows: cw*8 .. cw*8+7
        float4 au[8], aw[8];
        #pragma unroll
        for (int ii = 0; ii < 8; ii++) {
            int c = cw * 8 + ii;
            float4 vv = *(const float4*)&v[(base + c) * 128 + d32 * 4];
            float4 kk = *(const float4*)&g_kn[(base + c) * 128 + d32 * 4];
            float bc = beta_s[c];
            au[ii] = make_float4(vv.x * bc, vv.y * bc, vv.z * bc, vv.w * bc);
            aw[ii] = make_float4(kk.x * bc, kk.y * bc, kk.z * bc, kk.w * bc);
        }
        for (int t = 0; t < 32; t++) {
            float bt = beta_s[t];
            float4 vv = *(const float4*)&v[(base + t) * 128 + d32 * 4];
            float4 kk = *(const float4*)&g_kn[(base + t) * 128 + d32 * 4];
            vv.x *= bt; vv.y *= bt; vv.z *= bt; vv.w *= bt;
            kk.x *= bt; kk.y *= bt; kk.z *= bt; kk.w *= bt;
            #pragma unroll
            for (int ii = 0; ii < 8; ii++) {
                float a = A[(cw * 8 + ii) * 33 + t];
                au[ii].x += a * vv.x; au[ii].y += a * vv.y;
                au[ii].z += a * vv.z; au[ii].w += a * vv.w;
                aw[ii].x += a * kk.x; aw[ii].y += a * kk.y;
                aw[ii].z += a * kk.z; aw[ii].w += a * kk.w;
            }
        }
        #pragma unroll
        for (int ii = 0; ii < 8; ii++) {
            int c = cw * 8 + ii;
            *(float4*)&g_u[(base + c) * 128 + d32 * 4] = au[ii];
            // stage w transposed: knT[d*33 + c]
            knT[(d32 * 4 + 0) * 33 + c] = aw[ii].x;
            knT[(d32 * 4 + 1) * 33 + c] = aw[ii].y;
            knT[(d32 * 4 + 2) * 33 + c] = aw[ii].z;
            knT[(d32 * 4 + 3) * 33 + c] = aw[ii].w;
        }
    }
    __syncthreads();
    {
        float* gw = g_wt + base * 128;
        for (int idx = tid; idx < 4096; idx += 128) {
            int d = idx >> 5, c = idx & 31;
            gw[idx] = knT[d * 33 + c];
        }
    }
}

// ---------------------------------------------------------------------------
// cp.async helpers
// ---------------------------------------------------------------------------
__device__ __forceinline__ void cpa16(float* s, const void* g) {
    unsigned a = (unsigned)__cvta_generic_to_shared(s);
    asm volatile("cp.async.cg.shared.global [%0], [%1], 16;" :: "r"(a), "l"(g));
}
__device__ __forceinline__ void cpa_commit() {
    asm volatile("cp.async.commit_group;");
}
__device__ __forceinline__ void cpa_wait_all() {
    asm volatile("cp.async.wait_group 0;");
}

// Buffer layout (floats, per buffer):
//   qT[4096] @0, k[4096] @4096, wT[4096] @8192, attnT[1024] @12288, u0[1024] @13312
#define OFF_Q    0
#define OFF_K    4096
#define OFF_W    8192
#define OFF_A    12288
#define OFF_U0   13312
#define BUF_FLOATS 14336

// ---------------------------------------------------------------------------
// Kernel 2: sequential scan over chunks. grid (NSPLIT, BH), 256 threads.
// f32x2 packed FMA everywhere; qT/wT/attnT layouts give pair-adjacent operands.
// ---------------------------------------------------------------------------
__global__ void __launch_bounds__(256, 1) scan_kernel(float* __restrict__ out) {
    extern __shared__ float sm[];
    float* S  = sm;                             // [d=128][j=32]
    float* us = sm + 4096 + 2 * BUF_FLOATS;     // [c=32][j=32]

    int tid = threadIdx.x;
    int bh = blockIdx.y;
    int dvoff = blockIdx.x * 32;
    int j = tid & 31;              // dv column within slice
    int cg = tid >> 5;             // warp id 0..7: rows c = cg*4 .. cg*4+3

    const float4* gq4 = (const float4*)(g_qt + (size_t)bh * LSEQ * D);
    const float4* gk4 = (const float4*)(g_kn + (size_t)bh * LSEQ * D);
    const float4* gw4 = (const float4*)(g_wt + (size_t)bh * LSEQ * D);
    const float4* ga4 = (const float4*)(g_attn + (size_t)bh * NCHUNK * 1024);
    const float*  gu  = g_u + (size_t)bh * LSEQ * D;
    float* gout = out + (size_t)bh * LSEQ * D + dvoff;

    // ---- prefetch chunk 0 into buffer 0
    {
        float* B = sm + 4096;
        for (int i = tid; i < 1024; i += 256) {
            cpa16(B + OFF_Q + 4 * i, gq4 + i);
            cpa16(B + OFF_K + 4 * i, gk4 + i);
            cpa16(B + OFF_W + 4 * i, gw4 + i);
        }
        cpa16(B + OFF_A + 4 * tid, ga4 + tid);
        {
            int row = tid >> 3, c4 = tid & 7;
            cpa16(B + OFF_U0 + 4 * tid,
                  gu + (size_t)row * 128 + dvoff + c4 * 4);
        }
        cpa_commit();
    }

    for (int i = tid; i < 4096; i += 256) S[i] = 0.0f;

    for (int ch = 0; ch < NCHUNK; ch++) {
        cpa_wait_all();
        __syncthreads();   // current buffer ready; prev chunk's S update done

        float* B = sm + 4096 + (ch & 1) * BUF_FLOATS;
        const ulonglong2* qT2 = (const ulonglong2*)(B + OFF_Q);
        const ulonglong2* kk2 = (const ulonglong2*)(B + OFF_K);
        const ulonglong2* wT2 = (const ulonglong2*)(B + OFF_W);
        const ulonglong2* aT2 = (const ulonglong2*)(B + OFF_A);
        const float*      u0b = B + OFF_U0;

        // ---- prefetch chunk ch+1 into the other buffer (overlaps compute)
        if (ch + 1 < NCHUNK) {
            float* P = sm + 4096 + ((ch + 1) & 1) * BUF_FLOATS;
            size_t off4 = (size_t)(ch + 1) * 1024;
            for (int i = tid; i < 1024; i += 256) {
                cpa16(P + OFF_Q + 4 * i, gq4 + off4 + i);
                cpa16(P + OFF_K + 4 * i, gk4 + off4 + i);
                cpa16(P + OFF_W + 4 * i, gw4 + off4 + i);
            }
            cpa16(P + OFF_A + 4 * tid, ga4 + (size_t)(ch + 1) * 256 + tid);
            {
                int row = tid >> 3, c4 = tid & 7;
                cpa16(P + OFF_U0 + 4 * tid,
                      gu + (size_t)((ch + 1) * 32 + row) * 128 + dvoff + c4 * 4);
            }
            cpa_commit();
        }

        // ---- fused step: MW = w@S, O = q@S (packed pairs over c)
        ull MW01 = 0, MW23 = 0, O01 = 0, O23 = 0;
        #pragma unroll 4
        for (int d = 0; d < 128; d++) {
            ull sd = packdup(S[d * 32 + j]);
            ulonglong2 wv = wT2[d * 8 + cg];   // (w[c0],w[c1]) , (w[c2],w[c3]) at this d
            ulonglong2 qv = qT2[d * 8 + cg];
            fma2(MW01, wv.x, sd);
            fma2(MW23, wv.y, sd);
            fma2(O01, qv.x, sd);
            fma2(O23, qv.y, sd);
        }
        {   // u_c = u0_c - MW_c  -> us
            float m0, m1, m2, m3;
            unpack2(MW01, m0, m1);
            unpack2(MW23, m2, m3);
            us[(cg * 4 + 0) * 32 + j] = u0b[(cg * 4 + 0) * 32 + j] - m0;
            us[(cg * 4 + 1) * 32 + j] = u0b[(cg * 4 + 1) * 32 + j] - m1;
            us[(cg * 4 + 2) * 32 + j] = u0b[(cg * 4 + 2) * 32 + j] - m2;
            us[(cg * 4 + 3) * 32 + j] = u0b[(cg * 4 + 3) * 32 + j] - m3;
        }
        __syncthreads();   // us ready; all S reads of this chunk complete

        // ---- O += attn^T-contracted u:  o_c += sum_t attnT[t][c] * u[t]
        #pragma unroll 4
        for (int t = 0; t < 32; t++) {
            ull ud = packdup(us[t * 32 + j]);
            ulonglong2 av = aT2[t * 8 + cg];
            fma2(O01, av.x, ud);
            fma2(O23, av.y, ud);
        }
        {
            float o0, o1, o2, o3;
            unpack2(O01, o0, o1);
            unpack2(O23, o2, o3);
            gout[(size_t)(ch * 32 + cg * 4 + 0) * 128 + j] = o0;
            gout[(size_t)(ch * 32 + cg * 4 + 1) * 128 + j] = o1;
            gout[(size_t)(ch * 32 + cg * 4 + 2) * 128 + j] = o2;
            gout[(size_t)(ch * 32 + cg * 4 + 3) * 128 + j] = o3;
        }

        // ---- S += k^T @ u  (16 disjoint S rows per warp, packed over d pairs)
        int dbase = cg * 16;
        ull SP[8];
        #pragma unroll
        for (int p = 0; p < 8; p++)
            SP[p] = pack2(S[(dbase + 2 * p) * 32 + j],
                          S[(dbase + 2 * p + 1) * 32 + j]);
        #pragma unroll 2
        for (int c = 0; c < 32; c++) {
            ull ud = packdup(us[c * 32 + j]);
            #pragma unroll
            for (int qq = 0; qq < 4; qq++) {
                // k row-major: k[c][dbase+4q .. +3] => pairs (.x,.y)
                ulonglong2 kv = kk2[c * 32 + cg * 4 + qq];
                fma2(SP[2 * qq + 0], kv.x, ud);
                fma2(SP[2 * qq + 1], kv.y, ud);
            }
        }
        #pragma unroll
        for (int p = 0; p < 8; p++) {
            float a, b;
            unpack2(SP[p], a, b);
            S[(dbase + 2 * p) * 32 + j]     = a;
            S[(dbase + 2 * p + 1) * 32 + j] = b;
        }
        // next iteration's top barrier orders these writes before S reads
    }
}

// ---------------------------------------------------------------------------
extern "C" void kernel_launch(void* const* d_in, const int* in_sizes, int n_in,
                              void* d_out, int out_size) {
    const float* q    = (const float*)d_in[0];
    const float* k    = (const float*)d_in[1];
    const float* v    = (const float*)d_in[2];
    const float* beta = (const float*)d_in[3];
    float* out = (float*)d_out;

    chunk_kernel<<<BH * NCHUNK, 128>>>(q, k, v, beta);

    const int smem_bytes = (4096 + 2 * BUF_FLOATS + 1024) * sizeof(float); // 132 KB
    cudaFuncSetAttribute(scan_kernel,
                         cudaFuncAttributeMaxDynamicSharedMemorySize, smem_bytes);
    scan_kernel<<<dim3(NSPLIT, BH), 256, smem_bytes>>>(out);
}